// round 9
// baseline (speedup 1.0000x reference)
#include <cuda_runtime.h>
#include <cuda_bf16.h>

// SilkNNUE: out[r] = MLP( relu( sum_{k<29} emb[x[r,k]] ) )
// Layer2: 128->32 (+b2), CReLU -> 64
// Layer3: 64->32  (+b3), CReLU -> 64
// Layer4: 64->1
//
// R3: batch 8 rows per warp through gather + MLP so each weight LDS feeds
// 8 rows (8x less smem weight traffic — the R2 L1TEX bottleneck) and the
// gather has MLP=8 loads in flight.

#define WARPS_PER_BLOCK 8
#define ROWS_PER_WARP   8
#define ROWS_PER_BLOCK  (WARPS_PER_BLOCK * ROWS_PER_WARP)
#define FULLMASK 0xffffffffu

__global__ __launch_bounds__(256) void silk_nnue_kernel(
    const int*   __restrict__ x,     // (nrows, 32) int32, first 29 cols used
    const float* __restrict__ emb,   // (14848, 128)
    const float* __restrict__ w2,    // (32, 128)
    const float* __restrict__ b2,    // (32,)
    const float* __restrict__ w3,    // (32, 64)
    const float* __restrict__ b3,    // (32,)
    const float* __restrict__ w4,    // (1, 64)
    float*       __restrict__ out,   // (nrows,)
    int nrows)
{
    // Transposed weights: consecutive lanes read consecutive floats (no conflicts).
    __shared__ float w2t[128 * 32];   // w2t[k*32 + j] = w2[j*128 + k]
    __shared__ float w3t[64 * 32];    // w3t[k*32 + i] = w3[i*64 + k]
    __shared__ float b2s[32], b3s[32], w4s[64];
    __shared__ float hsm[WARPS_PER_BLOCK][ROWS_PER_WARP][128];

    const int tid = threadIdx.x;

    for (int i = tid; i < 32 * 128; i += 256) {
        int j = i >> 7, k = i & 127;
        w2t[k * 32 + j] = w2[i];
    }
    for (int i = tid; i < 32 * 64; i += 256) {
        int j = i >> 6, k = i & 63;
        w3t[k * 32 + j] = w3[i];
    }
    if (tid < 32) { b2s[tid] = b2[tid]; b3s[tid] = b3[tid]; }
    if (tid < 64) { w4s[tid] = w4[tid]; }
    __syncthreads();

    const int warp = tid >> 5;
    const int lane = tid & 31;
    const int row0 = blockIdx.x * ROWS_PER_BLOCK + warp * ROWS_PER_WARP;
    if (row0 >= nrows) return;
    const int rlast = nrows - 1;

    const float4* __restrict__ emb4 = (const float4*)emb;

    // ---- index prefetch: lane l holds column l's index for each of 8 rows ----
    int myidx[ROWS_PER_WARP];
    #pragma unroll
    for (int r = 0; r < ROWS_PER_WARP; r++) {
        const int rr = min(row0 + r, rlast);
        myidx[r] = x[rr * 32 + lane];
    }

    // ---- gather-sum: 8 independent LDG.128 in flight per k-step ----
    float4 acc[ROWS_PER_WARP];
    #pragma unroll
    for (int r = 0; r < ROWS_PER_WARP; r++)
        acc[r] = make_float4(0.f, 0.f, 0.f, 0.f);

    #pragma unroll 1
    for (int k = 0; k < 29; k++) {
        #pragma unroll
        for (int r = 0; r < ROWS_PER_WARP; r++) {
            const int idx = __shfl_sync(FULLMASK, myidx[r], k);
            const float4 e = emb4[(long)idx * 32 + lane];  // coalesced 512B/warp
            acc[r].x += e.x; acc[r].y += e.y;
            acc[r].z += e.z; acc[r].w += e.w;
        }
    }

    // ---- ReLU + stage h for all 8 rows ----
    #pragma unroll
    for (int r = 0; r < ROWS_PER_WARP; r++) {
        float4 hv;
        hv.x = fmaxf(acc[r].x, 0.f);
        hv.y = fmaxf(acc[r].y, 0.f);
        hv.z = fmaxf(acc[r].z, 0.f);
        hv.w = fmaxf(acc[r].w, 0.f);
        ((float4*)hsm[warp][r])[lane] = hv;   // conflict-free STS.128
    }
    __syncwarp();

    // ---- layer 2: each weight LDS amortized over 8 rows ----
    float s[ROWS_PER_WARP];
    #pragma unroll
    for (int r = 0; r < ROWS_PER_WARP; r++) s[r] = 0.f;

    const float* __restrict__ w2p = w2t + lane;
    #pragma unroll 4
    for (int k = 0; k < 128; k += 4) {
        const float wa = w2p[(k + 0) * 32];
        const float wb = w2p[(k + 1) * 32];
        const float wc = w2p[(k + 2) * 32];
        const float wd = w2p[(k + 3) * 32];
        #pragma unroll
        for (int r = 0; r < ROWS_PER_WARP; r++) {
            const float4 hh = *(const float4*)(&hsm[warp][r][k]);  // broadcast
            s[r] += hh.x * wa + hh.y * wb + hh.z * wc + hh.w * wd;
        }
    }
    float o2[ROWS_PER_WARP];
    #pragma unroll
    for (int r = 0; r < ROWS_PER_WARP; r++)
        o2[r] = b2s[lane] + s[r];

    // ---- layer 3 (fused CReLU), weights amortized over 8 rows ----
    float t0[ROWS_PER_WARP], t1[ROWS_PER_WARP];
    #pragma unroll
    for (int r = 0; r < ROWS_PER_WARP; r++) { t0[r] = 0.f; t1[r] = 0.f; }

    const float* __restrict__ w3p = w3t + lane;
    #pragma unroll 4
    for (int j = 0; j < 32; j++) {
        const float wa = w3p[j * 32];
        const float wb = w3p[(32 + j) * 32];
        #pragma unroll
        for (int r = 0; r < ROWS_PER_WARP; r++) {
            const float t = __shfl_sync(FULLMASK, o2[r], j);
            t0[r] += fmaxf(t, 0.f)  * wa;
            t1[r] += fmaxf(-t, 0.f) * wb;
        }
    }

    // ---- layer 4 (fused CReLU) + warp reduction per row ----
    #pragma unroll
    for (int r = 0; r < ROWS_PER_WARP; r++) {
        const float o3 = b3s[lane] + t0[r] + t1[r];
        float g = fmaxf(o3, 0.f) * w4s[lane] + fmaxf(-o3, 0.f) * w4s[32 + lane];
        #pragma unroll
        for (int off = 16; off; off >>= 1)
            g += __shfl_xor_sync(FULLMASK, g, off);
        if (lane == 0 && (row0 + r) < nrows) out[row0 + r] = g;
    }
}

extern "C" void kernel_launch(void* const* d_in, const int* in_sizes, int n_in,
                              void* d_out, int out_size)
{
    const int*   x   = (const int*)  d_in[0];
    const float* emb = (const float*)d_in[1];
    const float* w2  = (const float*)d_in[2];
    const float* b2  = (const float*)d_in[3];
    const float* w3  = (const float*)d_in[4];
    const float* b3  = (const float*)d_in[5];
    const float* w4  = (const float*)d_in[6];
    float* out = (float*)d_out;

    const int nrows  = in_sizes[0] / 32;
    const int blocks = (nrows + ROWS_PER_BLOCK - 1) / ROWS_PER_BLOCK;
    silk_nnue_kernel<<<blocks, 256>>>(x, emb, w2, b2, w3, b3, w4, out, nrows);
}

// round 10
// speedup vs baseline: 1.2705x; 1.2705x over previous
#include <cuda_runtime.h>
#include <cuda_fp16.h>
#include <cuda_bf16.h>

// SilkNNUE: out[r] = MLP( relu( sum_{k<29} emb[x[r,k]] ) )
// R9: fp16-compressed embedding table (device-global scratch, converted by a
// tiny pre-kernel each launch). One LDG.128 now gathers TWO rows (16 lanes
// per row), halving gather L1 wavefronts and L2 bytes. fp32 accumulation
// via packed add.rn.f32x2. MLP layers unchanged (8-row amortized weights).

#define VOCAB 14848
#define EMBD  128
#define WARPS_PER_BLOCK 8
#define ROWS_PER_WARP   8
#define ROWS_PER_BLOCK  (WARPS_PER_BLOCK * ROWS_PER_WARP)
#define FULLMASK 0xffffffffu

__device__ __half g_embh[VOCAB * EMBD];   // 3.8 MB static scratch (allowed)

// ---- pre-pass: fp32 emb -> fp16 table (8 elems / thread, exact grid) ----
__global__ __launch_bounds__(256) void convert_emb_kernel(const float* __restrict__ emb)
{
    const int i = blockIdx.x * 256 + threadIdx.x;       // one per 8 elements
    const float4* p = (const float4*)emb + (size_t)i * 2;
    const float4 a = p[0], b = p[1];
    __half2 h0 = __floats2half2_rn(a.x, a.y);
    __half2 h1 = __floats2half2_rn(a.z, a.w);
    __half2 h2 = __floats2half2_rn(b.x, b.y);
    __half2 h3 = __floats2half2_rn(b.z, b.w);
    uint4 o;
    o.x = *(unsigned*)&h0; o.y = *(unsigned*)&h1;
    o.z = *(unsigned*)&h2; o.w = *(unsigned*)&h3;
    ((uint4*)g_embh)[i] = o;
}

// packed fp32x2 accumulate (Blackwell f32x2 pipe)
__device__ __forceinline__ void fadd2(unsigned long long& acc, float x, float y)
{
    unsigned long long v;
    asm("mov.b64 %0, {%1, %2};" : "=l"(v) : "f"(x), "f"(y));
    asm("add.rn.f32x2 %0, %0, %1;" : "+l"(acc) : "l"(v));
}
__device__ __forceinline__ float2 unpack2(unsigned long long acc)
{
    float2 f;
    asm("mov.b64 {%0, %1}, %2;" : "=f"(f.x), "=f"(f.y) : "l"(acc));
    return f;
}

__global__ __launch_bounds__(256) void silk_nnue_kernel(
    const int*   __restrict__ x,     // (nrows, 32) int32, first 29 cols used
    const float* __restrict__ w2,    // (32, 128)
    const float* __restrict__ b2,    // (32,)
    const float* __restrict__ w3,    // (32, 64)
    const float* __restrict__ b3,    // (32,)
    const float* __restrict__ w4,    // (1, 64)
    float*       __restrict__ out,   // (nrows,)
    int nrows)
{
    __shared__ float w2t[128 * 32];   // w2t[k*32 + j] = w2[j*128 + k]
    __shared__ float w3t[64 * 32];    // w3t[k*32 + i] = w3[i*64 + k]
    __shared__ float b2s[32], b3s[32], w4s[64];
    __shared__ float hsm[WARPS_PER_BLOCK][ROWS_PER_WARP][128];

    const int tid = threadIdx.x;

    for (int i = tid; i < 32 * 128; i += 256) {
        int j = i >> 7, k = i & 127;
        w2t[k * 32 + j] = w2[i];
    }
    for (int i = tid; i < 32 * 64; i += 256) {
        int j = i >> 6, k = i & 63;
        w3t[k * 32 + j] = w3[i];
    }
    if (tid < 32) { b2s[tid] = b2[tid]; b3s[tid] = b3[tid]; }
    if (tid < 64) { w4s[tid] = w4[tid]; }
    __syncthreads();

    const int warp = tid >> 5;
    const int lane = tid & 31;
    const int row0 = blockIdx.x * ROWS_PER_BLOCK + warp * ROWS_PER_WARP;
    if (row0 >= nrows) return;
    const int rlast = nrows - 1;

    const int sub = lane & 15;    // position within row (8 halves = 16B chunk)
    const int hi  = lane >> 4;    // which row of the pair this lane gathers

    // ---- index prefetch: lane l holds column l's index for each of 8 rows ----
    int myidx[ROWS_PER_WARP];
    #pragma unroll
    for (int r = 0; r < ROWS_PER_WARP; r++) {
        const int rr = min(row0 + r, rlast);
        myidx[r] = x[rr * 32 + lane];
    }

    // ---- gather-sum: one LDG.128 covers 2 rows (16 lanes each) ----
    // acc[p][q]: pair p (rows 2p, 2p+1), q-th float2 of this lane's 8 values
    unsigned long long acc[4][4];
    #pragma unroll
    for (int p = 0; p < 4; p++)
        #pragma unroll
        for (int q = 0; q < 4; q++) acc[p][q] = 0ull;

    const __half* __restrict__ embh = g_embh;

    #pragma unroll 1
    for (int k = 0; k < 29; k++) {
        #pragma unroll
        for (int p = 0; p < 4; p++) {
            const int ia = __shfl_sync(FULLMASK, myidx[2 * p],     k);
            const int ib = __shfl_sync(FULLMASK, myidx[2 * p + 1], k);
            const int idx = hi ? ib : ia;
            const uint4 v = *(const uint4*)(embh + (size_t)idx * EMBD + sub * 8);
            float2 f;
            f = __half22float2(*(const __half2*)&v.x); fadd2(acc[p][0], f.x, f.y);
            f = __half22float2(*(const __half2*)&v.y); fadd2(acc[p][1], f.x, f.y);
            f = __half22float2(*(const __half2*)&v.z); fadd2(acc[p][2], f.x, f.y);
            f = __half22float2(*(const __half2*)&v.w); fadd2(acc[p][3], f.x, f.y);
        }
    }

    // ---- ReLU + stage h: lane owns values [sub*8, sub*8+8) of row 2p+hi ----
    #pragma unroll
    for (int p = 0; p < 4; p++) {
        const float2 f0 = unpack2(acc[p][0]);
        const float2 f1 = unpack2(acc[p][1]);
        const float2 f2 = unpack2(acc[p][2]);
        const float2 f3 = unpack2(acc[p][3]);
        float4 lo, hi4;
        lo.x  = fmaxf(f0.x, 0.f); lo.y  = fmaxf(f0.y, 0.f);
        lo.z  = fmaxf(f1.x, 0.f); lo.w  = fmaxf(f1.y, 0.f);
        hi4.x = fmaxf(f2.x, 0.f); hi4.y = fmaxf(f2.y, 0.f);
        hi4.z = fmaxf(f3.x, 0.f); hi4.w = fmaxf(f3.y, 0.f);
        float* dst = &hsm[warp][2 * p + hi][sub * 8];
        ((float4*)dst)[0] = lo;
        ((float4*)dst)[1] = hi4;
    }
    __syncwarp();

    // ---- layer 2: each weight LDS amortized over 8 rows ----
    float s[ROWS_PER_WARP];
    #pragma unroll
    for (int r = 0; r < ROWS_PER_WARP; r++) s[r] = 0.f;

    const float* __restrict__ w2p = w2t + lane;
    #pragma unroll 4
    for (int k = 0; k < 128; k += 4) {
        const float wa = w2p[(k + 0) * 32];
        const float wb = w2p[(k + 1) * 32];
        const float wc = w2p[(k + 2) * 32];
        const float wd = w2p[(k + 3) * 32];
        #pragma unroll
        for (int r = 0; r < ROWS_PER_WARP; r++) {
            const float4 hh = *(const float4*)(&hsm[warp][r][k]);  // broadcast
            s[r] += hh.x * wa + hh.y * wb + hh.z * wc + hh.w * wd;
        }
    }
    float o2[ROWS_PER_WARP];
    #pragma unroll
    for (int r = 0; r < ROWS_PER_WARP; r++)
        o2[r] = b2s[lane] + s[r];

    // ---- layer 3 (fused CReLU), weights amortized over 8 rows ----
    float t0[ROWS_PER_WARP], t1[ROWS_PER_WARP];
    #pragma unroll
    for (int r = 0; r < ROWS_PER_WARP; r++) { t0[r] = 0.f; t1[r] = 0.f; }

    const float* __restrict__ w3p = w3t + lane;
    #pragma unroll 4
    for (int j = 0; j < 32; j++) {
        const float wa = w3p[j * 32];
        const float wb = w3p[(32 + j) * 32];
        #pragma unroll
        for (int r = 0; r < ROWS_PER_WARP; r++) {
            const float t = __shfl_sync(FULLMASK, o2[r], j);
            t0[r] += fmaxf(t, 0.f)  * wa;
            t1[r] += fmaxf(-t, 0.f) * wb;
        }
    }

    // ---- layer 4 (fused CReLU) + warp reduction per row ----
    #pragma unroll
    for (int r = 0; r < ROWS_PER_WARP; r++) {
        const float o3 = b3s[lane] + t0[r] + t1[r];
        float g = fmaxf(o3, 0.f) * w4s[lane] + fmaxf(-o3, 0.f) * w4s[32 + lane];
        #pragma unroll
        for (int off = 16; off; off >>= 1)
            g += __shfl_xor_sync(FULLMASK, g, off);
        if (lane == 0 && (row0 + r) < nrows) out[row0 + r] = g;
    }
}

extern "C" void kernel_launch(void* const* d_in, const int* in_sizes, int n_in,
                              void* d_out, int out_size)
{
    const int*   x   = (const int*)  d_in[0];
    const float* emb = (const float*)d_in[1];
    const float* w2  = (const float*)d_in[2];
    const float* b2  = (const float*)d_in[3];
    const float* w3  = (const float*)d_in[4];
    const float* b3  = (const float*)d_in[5];
    const float* w4  = (const float*)d_in[6];
    float* out = (float*)d_out;

    // fp32 -> fp16 table (exact grid: VOCAB*EMBD/8 threads)
    convert_emb_kernel<<<(VOCAB * EMBD / 8 + 255) / 256, 256>>>(emb);

    const int nrows  = in_sizes[0] / 32;
    const int blocks = (nrows + ROWS_PER_BLOCK - 1) / ROWS_PER_BLOCK;
    silk_nnue_kernel<<<blocks, 256>>>(x, w2, b2, w3, b3, w4, out, nrows);
}

// round 11
// speedup vs baseline: 1.3065x; 1.0283x over previous
#include <cuda_runtime.h>
#include <cuda_fp16.h>
#include <cuda_bf16.h>

// SilkNNUE: out[r] = MLP( relu( sum_{k<29} emb[x[r,k]] ) )
// R10: (a) h staged in smem as fp16 -> layer2 h-broadcast LDS phases halved
//      (b) layer2 uses packed fma.rn.f32x2 with float2-packed w2
//      (c) gather split into two 4-row passes (acc regs 32->16) +
//          launch_bounds(256,4) -> 4 CTAs/SM (was 3)

#define VOCAB 14848
#define EMBD  128
#define WARPS_PER_BLOCK 8
#define ROWS_PER_WARP   8
#define ROWS_PER_BLOCK  (WARPS_PER_BLOCK * ROWS_PER_WARP)
#define FULLMASK 0xffffffffu

typedef unsigned long long ull;

__device__ __half g_embh[VOCAB * EMBD];   // 3.8 MB static scratch

// ---- pre-pass: fp32 emb -> fp16 table ----
__global__ __launch_bounds__(256) void convert_emb_kernel(const float* __restrict__ emb)
{
    const int i = blockIdx.x * 256 + threadIdx.x;       // one per 8 elements
    const float4* p = (const float4*)emb + (size_t)i * 2;
    const float4 a = p[0], b = p[1];
    __half2 h0 = __floats2half2_rn(a.x, a.y);
    __half2 h1 = __floats2half2_rn(a.z, a.w);
    __half2 h2 = __floats2half2_rn(b.x, b.y);
    __half2 h3 = __floats2half2_rn(b.z, b.w);
    uint4 o;
    o.x = *(unsigned*)&h0; o.y = *(unsigned*)&h1;
    o.z = *(unsigned*)&h2; o.w = *(unsigned*)&h3;
    ((uint4*)g_embh)[i] = o;
}

// ---- packed fp32x2 helpers (Blackwell f32x2 pipe) ----
__device__ __forceinline__ ull pack2(float x, float y)
{
    ull v;
    asm("mov.b64 %0, {%1, %2};" : "=l"(v) : "f"(x), "f"(y));
    return v;
}
__device__ __forceinline__ void fadd2(ull& acc, float x, float y)
{
    ull v = pack2(x, y);
    asm("add.rn.f32x2 %0, %0, %1;" : "+l"(acc) : "l"(v));
}
__device__ __forceinline__ void ffma2(ull& acc, ull a, ull b)
{
    asm("fma.rn.f32x2 %0, %1, %2, %0;" : "+l"(acc) : "l"(a), "l"(b));
}
__device__ __forceinline__ float2 unpack2(ull acc)
{
    float2 f;
    asm("mov.b64 {%0, %1}, %2;" : "=f"(f.x), "=f"(f.y) : "l"(acc));
    return f;
}

__global__ __launch_bounds__(256, 4) void silk_nnue_kernel(
    const int*   __restrict__ x,     // (nrows, 32) int32, first 29 cols used
    const float* __restrict__ w2,    // (32, 128)
    const float* __restrict__ b2,    // (32,)
    const float* __restrict__ w3,    // (32, 64)
    const float* __restrict__ b3,    // (32,)
    const float* __restrict__ w4,    // (1, 64)
    float*       __restrict__ out,   // (nrows,)
    int nrows)
{
    // w2 packed by k-pairs: w2q[k2*32 + j] = (w2[j][2k2], w2[j][2k2+1])
    __shared__ float2 w2q[64 * 32];                       // 16 KB
    __shared__ float  w3t[64 * 32];                       // 8 KB; w3t[k*32+i]=w3[i*64+k]
    __shared__ float  b2s[32], b3s[32], w4s[64];
    __shared__ __align__(16) __half hsm[WARPS_PER_BLOCK][ROWS_PER_WARP][128]; // 16 KB

    const int tid = threadIdx.x;

    for (int i = tid; i < 64 * 32; i += 256) {
        const int j = i & 31, k2 = i >> 5;
        w2q[i] = make_float2(w2[j * 128 + 2 * k2], w2[j * 128 + 2 * k2 + 1]);
    }
    for (int i = tid; i < 32 * 64; i += 256) {
        const int j = i >> 6, k = i & 63;
        w3t[k * 32 + j] = w3[i];
    }
    if (tid < 32) { b2s[tid] = b2[tid]; b3s[tid] = b3[tid]; }
    if (tid < 64) { w4s[tid] = w4[tid]; }
    __syncthreads();

    const int warp = tid >> 5;
    const int lane = tid & 31;
    const int row0 = blockIdx.x * ROWS_PER_BLOCK + warp * ROWS_PER_WARP;
    if (row0 >= nrows) return;
    const int rlast = nrows - 1;

    const int sub = lane & 15;    // 16B chunk within a 256B fp16 emb row
    const int hi  = lane >> 4;    // which row of a pair this lane gathers

    // ---- index prefetch: lane l holds column l's index for each of 8 rows ----
    int myidx[ROWS_PER_WARP];
    #pragma unroll
    for (int r = 0; r < ROWS_PER_WARP; r++) {
        const int rr = min(row0 + r, rlast);
        myidx[r] = x[rr * 32 + lane];
    }

    const __half* __restrict__ embh = g_embh;

    // ---- gather-sum in two passes of 2 row-pairs (acc regs halved) ----
    #pragma unroll
    for (int half = 0; half < 2; half++) {
        ull acc[2][4];
        #pragma unroll
        for (int p2 = 0; p2 < 2; p2++)
            #pragma unroll
            for (int q = 0; q < 4; q++) acc[p2][q] = 0ull;

        #pragma unroll 2
        for (int k = 0; k < 29; k++) {
            #pragma unroll
            for (int p2 = 0; p2 < 2; p2++) {
                const int p = half * 2 + p2;
                const int ia = __shfl_sync(FULLMASK, myidx[2 * p],     k);
                const int ib = __shfl_sync(FULLMASK, myidx[2 * p + 1], k);
                const int idx = hi ? ib : ia;
                const uint4 v = *(const uint4*)(embh + (size_t)idx * EMBD + sub * 8);
                float2 f;
                f = __half22float2(*(const __half2*)&v.x); fadd2(acc[p2][0], f.x, f.y);
                f = __half22float2(*(const __half2*)&v.y); fadd2(acc[p2][1], f.x, f.y);
                f = __half22float2(*(const __half2*)&v.z); fadd2(acc[p2][2], f.x, f.y);
                f = __half22float2(*(const __half2*)&v.w); fadd2(acc[p2][3], f.x, f.y);
            }
        }

        // ReLU + fp16 stage: lane owns values [sub*8, sub*8+8) of row 2p+hi
        #pragma unroll
        for (int p2 = 0; p2 < 2; p2++) {
            const int row = 2 * (half * 2 + p2) + hi;
            const float2 f0 = unpack2(acc[p2][0]);
            const float2 f1 = unpack2(acc[p2][1]);
            const float2 f2 = unpack2(acc[p2][2]);
            const float2 f3 = unpack2(acc[p2][3]);
            __half2 o0 = __floats2half2_rn(fmaxf(f0.x, 0.f), fmaxf(f0.y, 0.f));
            __half2 o1 = __floats2half2_rn(fmaxf(f1.x, 0.f), fmaxf(f1.y, 0.f));
            __half2 o2h = __floats2half2_rn(fmaxf(f2.x, 0.f), fmaxf(f2.y, 0.f));
            __half2 o3h = __floats2half2_rn(fmaxf(f3.x, 0.f), fmaxf(f3.y, 0.f));
            uint4 st;
            st.x = *(unsigned*)&o0;  st.y = *(unsigned*)&o1;
            st.z = *(unsigned*)&o2h; st.w = *(unsigned*)&o3h;
            *(uint4*)(&hsm[warp][row][sub * 8]) = st;   // STS.128, 16B/lane
        }
    }
    __syncwarp();

    // ---- layer 2: packed f32x2 FMA; h read as half2 broadcast (1 phase) ----
    ull s2[ROWS_PER_WARP];
    #pragma unroll
    for (int r = 0; r < ROWS_PER_WARP; r++) s2[r] = 0ull;

    #pragma unroll 4
    for (int k2 = 0; k2 < 64; k2++) {
        const float2 w = w2q[k2 * 32 + lane];            // conflict-free LDS.64
        const ull wv = pack2(w.x, w.y);
        #pragma unroll
        for (int r = 0; r < ROWS_PER_WARP; r++) {
            const __half2 hq = *(const __half2*)(&hsm[warp][r][2 * k2]); // broadcast
            const float2 hf = __half22float2(hq);
            ffma2(s2[r], pack2(hf.x, hf.y), wv);
        }
    }
    float o2[ROWS_PER_WARP];
    #pragma unroll
    for (int r = 0; r < ROWS_PER_WARP; r++) {
        const float2 f = unpack2(s2[r]);
        o2[r] = b2s[lane] + f.x + f.y;
    }

    // ---- layer 3 (fused CReLU), weights amortized over 8 rows ----
    float t0[ROWS_PER_WARP], t1[ROWS_PER_WARP];
    #pragma unroll
    for (int r = 0; r < ROWS_PER_WARP; r++) { t0[r] = 0.f; t1[r] = 0.f; }

    const float* __restrict__ w3p = w3t + lane;
    #pragma unroll 4
    for (int j = 0; j < 32; j++) {
        const float wa = w3p[j * 32];
        const float wb = w3p[(32 + j) * 32];
        #pragma unroll
        for (int r = 0; r < ROWS_PER_WARP; r++) {
            const float t = __shfl_sync(FULLMASK, o2[r], j);
            t0[r] += fmaxf(t, 0.f)  * wa;
            t1[r] += fmaxf(-t, 0.f) * wb;
        }
    }

    // ---- layer 4 (fused CReLU) + warp reduction per row ----
    #pragma unroll
    for (int r = 0; r < ROWS_PER_WARP; r++) {
        const float o3 = b3s[lane] + t0[r] + t1[r];
        float g = fmaxf(o3, 0.f) * w4s[lane] + fmaxf(-o3, 0.f) * w4s[32 + lane];
        #pragma unroll
        for (int off = 16; off; off >>= 1)
            g += __shfl_xor_sync(FULLMASK, g, off);
        if (lane == 0 && (row0 + r) < nrows) out[row0 + r] = g;
    }
}

extern "C" void kernel_launch(void* const* d_in, const int* in_sizes, int n_in,
                              void* d_out, int out_size)
{
    const int*   x   = (const int*)  d_in[0];
    const float* emb = (const float*)d_in[1];
    const float* w2  = (const float*)d_in[2];
    const float* b2  = (const float*)d_in[3];
    const float* w3  = (const float*)d_in[4];
    const float* b3  = (const float*)d_in[5];
    const float* w4  = (const float*)d_in[6];
    float* out = (float*)d_out;

    convert_emb_kernel<<<(VOCAB * EMBD / 8 + 255) / 256, 256>>>(emb);

    const int nrows  = in_sizes[0] / 32;
    const int blocks = (nrows + ROWS_PER_BLOCK - 1) / ROWS_PER_BLOCK;
    silk_nnue_kernel<<<blocks, 256>>>(x, w2, b2, w3, b3, w4, out, nrows);
}